// round 4
// baseline (speedup 1.0000x reference)
#include <cuda_runtime.h>

#define M 32
#define E_CONST 2.718281828459045f

// scratch: encoded per-mode minimum (monotonic unsigned encoding of float)
__device__ unsigned int g_min_enc[M];

__device__ __forceinline__ unsigned int enc_f(float f) {
    unsigned int b = __float_as_uint(f);
    return (b & 0x80000000u) ? ~b : (b | 0x80000000u);
}
__device__ __forceinline__ float dec_f(unsigned int k) {
    unsigned int b = (k & 0x80000000u) ? (k & 0x7FFFFFFFu) : ~k;
    return __uint_as_float(b);
}

// MUFU.EX2 — fast exp2 (the intrinsic __exp2f does not exist; this is the HW op)
__device__ __forceinline__ float ex2(float x) {
    float r;
    asm("ex2.approx.f32 %0, %1;" : "=f"(r) : "f"(x));
    return r;
}

__global__ void init_min_kernel() {
    if (threadIdx.x < M) g_min_enc[threadIdx.x] = 0xFFFFFFFFu;
}

// column-wise min over rows (deterministic: min is exact & commutative)
__global__ void col_min_kernel(const float* __restrict__ phi, int n_rows) {
    const int lane = threadIdx.x & 31;
    unsigned int local = 0xFFFFFFFFu;
    int gw = (blockIdx.x * blockDim.x + threadIdx.x) >> 5;
    int nw = (gridDim.x * blockDim.x) >> 5;
    for (int r = gw; r < n_rows; r += nw) {
        local = min(local, enc_f(phi[r * M + lane]));
    }
    __shared__ unsigned int smin[M];
    if (threadIdx.x < M) smin[threadIdx.x] = 0xFFFFFFFFu;
    __syncthreads();
    atomicMin(&smin[lane], local);
    __syncthreads();
    if (threadIdx.x < M) atomicMin(&g_min_enc[threadIdx.x], smin[threadIdx.x]);
}

// one warp per row; lane = mode index i
__global__ void __launch_bounds__(256) energy_kernel(
    const float* __restrict__ phi,
    const float* __restrict__ Gamma,
    const float* __restrict__ w,
    float* __restrict__ alphas,
    float* __restrict__ logits,
    int n_rows)
{
    const int lane = threadIdx.x & 31;
    const int warp = threadIdx.x >> 5;

    // symmetric gamma lookup row for this lane: g[j] = G(i=lane, j)
    float g[M];
#pragma unroll
    for (int j = 0; j < M; j++) {
        g[j] = (lane < j) ? Gamma[lane * M + j] : Gamma[j * M + lane];
    }
    const float wi = w[lane];
    const float mmin = dec_f(g_min_enc[lane]);

    __shared__ float lsh[8][M];

    int gw = blockIdx.x * (blockDim.x >> 5) + warp;
    int nw = gridDim.x * (blockDim.x >> 5);
    const float neg_t = -0.17677669529663687f;  // -1/sqrt(32)

    for (int r = gw; r < n_rows; r += nw) {
        float p = phi[r * M + lane];
        float phic = fmaxf(p - mmin + E_CONST, E_CONST);
        float li = __log2f(phic);
        lsh[warp][lane] = li;
        __syncwarp();

        // sum over ALL j of exp2(l_j + g*(l_i - l_j)); the j==i term equals
        // phic_i exactly (d=0), so full sum + w_i*phic_i gives
        // off-diag sum + (1+w_i)*phic_i.
        float sum = 0.f;
#pragma unroll
        for (int j = 0; j < M; j++) {
            float lj = lsh[warp][j];
            float arg = fmaf(g[j], li - lj, lj);
            sum += ex2(arg);
        }
        sum = fmaf(wi, phic, sum);

        float x = neg_t * sum;
        // warp log-softmax over 32 lanes
        float mx = x;
#pragma unroll
        for (int o = 16; o > 0; o >>= 1)
            mx = fmaxf(mx, __shfl_xor_sync(0xffffffffu, mx, o));
        float ex = __expf(x - mx);
        float s = ex;
#pragma unroll
        for (int o = 16; o > 0; o >>= 1)
            s += __shfl_xor_sync(0xffffffffu, s, o);
        float lg = (x - mx) - __logf(s);
        float al = ex * __frcp_rn(s);

        logits[r * M + lane] = lg;
        alphas[r * M + lane] = al;
        __syncwarp();  // lsh reuse safety for next row
    }
}

extern "C" void kernel_launch(void* const* d_in, const int* in_sizes, int n_in,
                              void* d_out, int out_size) {
    const float* phi   = (const float*)d_in[0];
    const float* Gamma = (const float*)d_in[1];
    const float* w     = (const float*)d_in[2];
    float* out = (float*)d_out;

    int n_rows = in_sizes[0] / M;
    float* alphas = out;
    float* logits = out + (out_size / 2);

    init_min_kernel<<<1, 32>>>();
    col_min_kernel<<<592, 256>>>(phi, n_rows);
    energy_kernel<<<1184, 256>>>(phi, Gamma, w, alphas, logits, n_rows);
}